// round 14
// baseline (speedup 1.0000x reference)
#include <cuda_runtime.h>
#include <cuda_fp16.h>
#include <math.h>
#include <stdint.h>

#define DMODEL 1024
#define SEQ    2048
#define BATCH  4
#define NHEADS 16
#define HDIM   64
#define DFF    4096
#define NROWS  8192
#define MODW   6144

// ---------------- scratch ----------------
__device__ float  g_mod[BATCH * MODW];
__device__ float  g_x2[(size_t)NROWS * DMODEL];
__device__ __half g_xnh[(size_t)NROWS * DMODEL];
__device__ __half g_qkvh[(size_t)NROWS * 3 * DMODEL];
__device__ __half g_attnh[(size_t)NROWS * DMODEL];
__device__ __half g_hh[(size_t)NROWS * DFF];
__device__ __half g_wqkvh[(size_t)DMODEL * 3 * DMODEL];
__device__ __half g_wouth[(size_t)DMODEL * DMODEL];
__device__ __half g_w1h[(size_t)DMODEL * DFF];
__device__ __half g_w2h[(size_t)DFF * DMODEL];

// ---------------- helpers ----------------
__device__ __forceinline__ float gelu_tanh(float x) {
    float x3 = x * x * x;
    float u = 0.7978845608028654f * (x + 0.044715f * x3);
    return 0.5f * x * (1.0f + tanhf(u));
}
__device__ __forceinline__ float ex2(float x) {
    float r; asm("ex2.approx.ftz.f32 %0, %1;" : "=f"(r) : "f"(x)); return r;
}
__device__ __forceinline__ uint32_t h2u(__half2 h) { return *(uint32_t*)&h; }
__device__ __forceinline__ uint32_t smem_u32(const void* p) {
    uint32_t a;
    asm("{ .reg .u64 t; cvta.to.shared.u64 t, %1; cvt.u32.u64 %0, t; }" : "=r"(a) : "l"(p));
    return a;
}
__device__ __forceinline__ void cpa16(uint32_t dst, const void* src) {
    asm volatile("cp.async.cg.shared.global [%0], [%1], 16;" :: "r"(dst), "l"(src) : "memory");
}
#define CP_COMMIT() asm volatile("cp.async.commit_group;" ::: "memory")
#define CP_WAIT(n)  asm volatile("cp.async.wait_group %0;" :: "n"(n) : "memory")

__device__ __forceinline__ void mma_f16(float c[4], const uint32_t a[4], const uint32_t b[2]) {
    asm volatile(
        "mma.sync.aligned.m16n8k16.row.col.f32.f16.f16.f32 "
        "{%0,%1,%2,%3}, {%4,%5,%6,%7}, {%8,%9}, {%0,%1,%2,%3};\n"
        : "+f"(c[0]), "+f"(c[1]), "+f"(c[2]), "+f"(c[3])
        : "r"(a[0]), "r"(a[1]), "r"(a[2]), "r"(a[3]), "r"(b[0]), "r"(b[1]));
}
__device__ __forceinline__ void ldsm_x4(uint32_t& r0, uint32_t& r1, uint32_t& r2, uint32_t& r3, uint32_t addr) {
    asm volatile("ldmatrix.sync.aligned.m8n8.x4.shared.b16 {%0,%1,%2,%3}, [%4];"
                 : "=r"(r0), "=r"(r1), "=r"(r2), "=r"(r3) : "r"(addr));
}
__device__ __forceinline__ void ldsm_x4_t(uint32_t& r0, uint32_t& r1, uint32_t& r2, uint32_t& r3, uint32_t addr) {
    asm volatile("ldmatrix.sync.aligned.m8n8.x4.trans.shared.b16 {%0,%1,%2,%3}, [%4];"
                 : "=r"(r0), "=r"(r1), "=r"(r2), "=r"(r3) : "r"(addr));
}

__device__ __forceinline__ void blockReduce2(float& a, float& b) {
    #pragma unroll
    for (int off = 16; off; off >>= 1) {
        a += __shfl_xor_sync(0xffffffffu, a, off);
        b += __shfl_xor_sync(0xffffffffu, b, off);
    }
    __shared__ float sa[8], sb[8];
    int w = threadIdx.x >> 5, l = threadIdx.x & 31;
    if (l == 0) { sa[w] = a; sb[w] = b; }
    __syncthreads();
    if (w == 0) {
        a = (l < 8) ? sa[l] : 0.0f;
        b = (l < 8) ? sb[l] : 0.0f;
        #pragma unroll
        for (int off = 4; off; off >>= 1) {
            a += __shfl_xor_sync(0xffffffffu, a, off);
            b += __shfl_xor_sync(0xffffffffu, b, off);
        }
        if (l == 0) { sa[0] = a; sb[0] = b; }
    }
    __syncthreads();
    a = sa[0]; b = sb[0];
}

// ---------------- 0) all four weights fp32 -> fp16 in one launch ----------------
#define R0 786432
#define R1 (R0 + 262144)
#define R2 (R1 + 1048576)
#define R3 (R2 + 1048576)
__global__ void cvth_all_kernel(const float* __restrict__ wqkv, const float* __restrict__ wout,
                                const float* __restrict__ w1, const float* __restrict__ w2) {
    int i = blockIdx.x * 256 + threadIdx.x;
    const float* in;
    __half* out;
    int j;
    if (i < R0)      { in = wqkv; out = g_wqkvh; j = i; }
    else if (i < R1) { in = wout; out = g_wouth; j = i - R0; }
    else if (i < R2) { in = w1;   out = g_w1h;   j = i - R1; }
    else             { in = w2;   out = g_w2h;   j = i - R2; }
    float4 v = ((const float4*)in)[j];
    __half2 lo = __floats2half2_rn(v.x, v.y);
    __half2 hi = __floats2half2_rn(v.z, v.w);
    ((uint2*)out)[j] = make_uint2(h2u(lo), h2u(hi));
}

// ---------------- 1) mod = c @ ada_W + ada_b ----------------
__global__ void mod_kernel(const float* __restrict__ c, const float* __restrict__ W,
                           const float* __restrict__ bias) {
    __shared__ float cs[1024];
    int b = blockIdx.y;
    int col = blockIdx.x * 256 + threadIdx.x;
    for (int i = threadIdx.x; i < 1024; i += 256) cs[i] = c[b * 1024 + i];
    __syncthreads();
    float acc = 0.0f;
    #pragma unroll 4
    for (int k = 0; k < 1024; k++) acc += cs[k] * W[(size_t)k * MODW + col];
    g_mod[b * MODW + col] = acc + bias[col];
}

// ---------------- 2) layernorm + modulate -> half ----------------
__global__ void ln_mod_kernel(const float* __restrict__ X, const float* __restrict__ w,
                              int shOff, int scOff, __half* __restrict__ out) {
    int row = blockIdx.x;
    int b = row >> 11;
    const float4* xr = (const float4*)(X + (size_t)row * DMODEL);
    float4 v = xr[threadIdx.x];
    float s = v.x + v.y + v.z + v.w;
    float ss = v.x * v.x + v.y * v.y + v.z * v.z + v.w * v.w;
    blockReduce2(s, ss);
    float mu = s * (1.0f / 1024.0f);
    float var = ss * (1.0f / 1024.0f) - mu * mu;
    float r = rsqrtf(var + 1e-5f);
    int d = threadIdx.x * 4;
    const float* mb = g_mod + b * MODW;
    float o0 = (v.x - mu) * r * w[d + 0] * (1.0f + mb[scOff + d + 0]) + mb[shOff + d + 0];
    float o1 = (v.y - mu) * r * w[d + 1] * (1.0f + mb[scOff + d + 1]) + mb[shOff + d + 1];
    float o2 = (v.z - mu) * r * w[d + 2] * (1.0f + mb[scOff + d + 2]) + mb[shOff + d + 2];
    float o3 = (v.w - mu) * r * w[d + 3] * (1.0f + mb[scOff + d + 3]) + mb[shOff + d + 3];
    ((uint2*)(out + (size_t)row * DMODEL))[threadIdx.x] =
        make_uint2(h2u(__floats2half2_rn(o0, o1)), h2u(__floats2half2_rn(o2, o3)));
}

// ---------------- 3) FP16 HMMA GEMM, 128x128x32, 4 warps, 64x64 warp tiles ----------
// MODE 0: Ch = acc (half)        MODE 1: Cf = res + gate * acc
// MODE 2: Ch = gelu(acc + bias)  MODE 3: Cf = res + gate * (acc + bias)
#define AH_STRIDE 40
#define BH_STRIDE 136

template<int MODE>
__global__ void __launch_bounds__(128, 2)
mma_gemm_h(const __half* __restrict__ A, const __half* __restrict__ B, void* __restrict__ Cp,
           int M, int N, int K,
           const float* __restrict__ res, const float* __restrict__ bias,
           const float* __restrict__ gate) {
    __shared__ __half As[2][128 * AH_STRIDE];
    __shared__ __half Bs[2][32 * BH_STRIDE];
    const int t = threadIdx.x;
    const int lane = t & 31, wid = t >> 5;          // 4 warps
    const int warp_m = wid & 1, warp_n = wid >> 1;  // 2 x 2 warp grid, 64x64 tiles
    const int rowBase = blockIdx.y * 128, colBase = blockIdx.x * 128;
    const int nk = K >> 5;

    float acc[4][8][4];
    #pragma unroll
    for (int mt = 0; mt < 4; mt++)
        #pragma unroll
        for (int nt = 0; nt < 8; nt++)
            #pragma unroll
            for (int f = 0; f < 4; f++) acc[mt][nt][f] = 0.0f;

    auto load_stage = [&](int kt, int buf) {
        #pragma unroll
        for (int i = 0; i < 4; i++) {
            int idx = t + i * 128;           // 0..511: 128 rows x 4 chunks(8h)
            int r = idx >> 2, q = idx & 3;
            cpa16(smem_u32(&As[buf][r * AH_STRIDE + q * 8]),
                  A + (size_t)(rowBase + r) * K + kt * 32 + q * 8);
        }
        #pragma unroll
        for (int i = 0; i < 4; i++) {
            int idx = t + i * 128;           // 0..511: 32 krows x 16 chunks
            int k = idx >> 4, cq = idx & 15;
            cpa16(smem_u32(&Bs[buf][k * BH_STRIDE + cq * 8]),
                  B + (size_t)(kt * 32 + k) * N + colBase + cq * 8);
        }
        CP_COMMIT();
    };

    load_stage(0, 0);
    for (int kt = 0; kt < nk; kt++) {
        if (kt + 1 < nk) {
            load_stage(kt + 1, (kt + 1) & 1);
            CP_WAIT(1);
        } else {
            CP_WAIT(0);
        }
        __syncthreads();
        const __half* as = As[kt & 1];
        const __half* bs = Bs[kt & 1];
        #pragma unroll
        for (int ks = 0; ks < 2; ks++) {
            uint32_t af[4][4], bw[4][4];
            #pragma unroll
            for (int mt = 0; mt < 4; mt++) {
                int row = warp_m * 64 + mt * 16 + (lane & 15);
                int col = ks * 16 + 8 * (lane >> 4);
                ldsm_x4(af[mt][0], af[mt][1], af[mt][2], af[mt][3],
                        smem_u32(&as[row * AH_STRIDE + col]));
            }
            #pragma unroll
            for (int np = 0; np < 4; np++) {
                int row = ks * 16 + (lane & 7) + 8 * ((lane >> 3) & 1);
                int col = warp_n * 64 + np * 16 + 8 * (lane >> 4);
                ldsm_x4_t(bw[np][0], bw[np][1], bw[np][2], bw[np][3],
                          smem_u32(&bs[row * BH_STRIDE + col]));
            }
            #pragma unroll
            for (int mt = 0; mt < 4; mt++)
                #pragma unroll
                for (int nt = 0; nt < 8; nt++)
                    mma_f16(acc[mt][nt], af[mt], &bw[nt >> 1][(nt & 1) * 2]);
        }
        __syncthreads();
    }

    #pragma unroll
    for (int mt = 0; mt < 4; mt++) {
        #pragma unroll
        for (int nt = 0; nt < 8; nt++) {
            #pragma unroll
            for (int half_ = 0; half_ < 2; half_++) {
                int gr = rowBase + warp_m * 64 + mt * 16 + (lane >> 2) + half_ * 8;
                int gc = colBase + warp_n * 64 + nt * 8 + (lane & 3) * 2;
                int bb = gr >> 11;
                size_t off = (size_t)gr * N + gc;
                float v0 = acc[mt][nt][half_ * 2 + 0];
                float v1 = acc[mt][nt][half_ * 2 + 1];
                if (MODE == 0) {
                    *(__half2*)((__half*)Cp + off) = __floats2half2_rn(v0, v1);
                } else if (MODE == 1) {
                    float* Cf = (float*)Cp;
                    Cf[off]     = res[off]     + gate[bb * MODW + gc]     * v0;
                    Cf[off + 1] = res[off + 1] + gate[bb * MODW + gc + 1] * v1;
                } else if (MODE == 2) {
                    *(__half2*)((__half*)Cp + off) =
                        __floats2half2_rn(gelu_tanh(v0 + bias[gc]), gelu_tanh(v1 + bias[gc + 1]));
                } else {
                    float* Cf = (float*)Cp;
                    Cf[off]     = res[off]     + gate[bb * MODW + gc]     * (v0 + bias[gc]);
                    Cf[off + 1] = res[off + 1] + gate[bb * MODW + gc + 1] * (v1 + bias[gc + 1]);
                }
            }
        }
    }
}

// ---------------- 4) rmsnorm + rope on q,k (half); q pre-scaled ----------------
__global__ void __launch_bounds__(1024)
rope_kernel(const float* __restrict__ qw, const float* __restrict__ kw,
            const float* __restrict__ cosb, const float* __restrict__ sinb) {
    __shared__ float sm[1024];
    __shared__ float part[32];
    int row = blockIdx.x;
    int s = row & (SEQ - 1);
    int t = threadIdx.x;
    int h = t >> 6, hd = t & 63;
    int wrp = t >> 5, lane = t & 31;
    float cs = cosb[s * HDIM + hd], sn = sinb[s * HDIM + hd];
    const float lscale = 0.125f * 1.4426950408889634f;
    #pragma unroll
    for (int which = 0; which < 2; which++) {
        size_t base = ((size_t)row * 3 + which) * DMODEL;
        float v = __half2float(g_qkvh[base + t]);
        float ss = v * v;
        #pragma unroll
        for (int off = 16; off; off >>= 1) ss += __shfl_xor_sync(0xffffffffu, ss, off);
        if (lane == 0) part[wrp] = ss;
        __syncthreads();
        float sumsq = part[2 * h] + part[2 * h + 1];
        float r = rsqrtf(sumsq * (1.0f / 64.0f) + 1e-6f);
        const float* ww = which ? kw : qw;
        float xn = v * r * ww[hd];
        sm[t] = xn;
        __syncthreads();
        float partner = sm[h * 64 + ((hd + 32) & 63)];
        float rot = (hd < 32) ? -partner : partner;
        float val = xn * cs + rot * sn;
        if (which == 0) val *= lscale;
        g_qkvh[base + t] = __float2half_rn(val);
        __syncthreads();
    }
}

// ---------------- 5) flash attention, fp16 HMMA (R8-exact: 64 q-rows, 128 thr) -------
#define KVS 72
#define ATTN_SMEM (2 * 2 * 64 * KVS * 2)

__global__ void __launch_bounds__(128)
attn_kernel() {
    extern __shared__ __half smemh[];
    __half* ksm = smemh;
    __half* vsm = smemh + 2 * 64 * KVS;

    const int qt = blockIdx.x, h = blockIdx.y, b = blockIdx.z;
    const int t = threadIdx.x;
    const int lane = t & 31, w = t >> 5;
    const int r0 = lane >> 2, q4 = lane & 3;

    const size_t kbase = ((size_t)(b * SEQ) * 3 + 1) * DMODEL + h * HDIM;
    const size_t vbase = kbase + DMODEL;
    const int qrow0 = b * SEQ + qt * 64 + w * 16;
    const __half* Qh = g_qkvh + (size_t)qrow0 * 3 * DMODEL + h * HDIM;

    uint32_t qf[4][4];
    #pragma unroll
    for (int s = 0; s < 4; s++) {
        int kk = 16 * s + 2 * q4;
        qf[s][0] = *(const uint32_t*)(Qh + (size_t)(r0    ) * 3072 + kk    );
        qf[s][1] = *(const uint32_t*)(Qh + (size_t)(r0 + 8) * 3072 + kk    );
        qf[s][2] = *(const uint32_t*)(Qh + (size_t)(r0    ) * 3072 + kk + 8);
        qf[s][3] = *(const uint32_t*)(Qh + (size_t)(r0 + 8) * 3072 + kk + 8);
    }

    float of[8][4];
    #pragma unroll
    for (int j = 0; j < 8; j++)
        #pragma unroll
        for (int f = 0; f < 4; f++) of[j][f] = 0.0f;
    float m0 = -1e30f, m1 = -1e30f, l0 = 0.0f, l1 = 0.0f;

    auto loadKV = [&](int k0, int buf) {
        #pragma unroll
        for (int i = 0; i < 4; i++) {
            int idx = t + i * 128;
            int row = idx >> 3, c = idx & 7;
            cpa16(smem_u32(&ksm[buf * 64 * KVS + row * KVS + c * 8]),
                  g_qkvh + kbase + (size_t)(k0 + row) * 3072 + c * 8);
            cpa16(smem_u32(&vsm[buf * 64 * KVS + row * KVS + c * 8]),
                  g_qkvh + vbase + (size_t)(k0 + row) * 3072 + c * 8);
        }
        CP_COMMIT();
    };

    loadKV(0, 0);
    for (int kt = 0; kt < SEQ / 64; kt++) {
        if (kt + 1 < SEQ / 64) {
            loadKV((kt + 1) * 64, (kt + 1) & 1);
            CP_WAIT(1);
        } else {
            CP_WAIT(0);
        }
        __syncthreads();
        const __half* kb = ksm + (kt & 1) * 64 * KVS;
        const __half* vb = vsm + (kt & 1) * 64 * KVS;

        float sf[8][4];
        #pragma unroll
        for (int j = 0; j < 8; j++)
            #pragma unroll
            for (int f = 0; f < 4; f++) sf[j][f] = 0.0f;
        #pragma unroll
        for (int s = 0; s < 4; s++) {
            #pragma unroll
            for (int np = 0; np < 4; np++) {
                uint32_t bw[4];
                int row = 16 * np + (lane & 7) + 8 * (lane >> 4);
                int col = 16 * s + 8 * ((lane >> 3) & 1);
                ldsm_x4(bw[0], bw[1], bw[2], bw[3], smem_u32(&kb[row * KVS + col]));
                mma_f16(sf[2 * np],     qf[s], &bw[0]);
                mma_f16(sf[2 * np + 1], qf[s], &bw[2]);
            }
        }

        float mx0 = -1e30f, mx1 = -1e30f;
        #pragma unroll
        for (int j = 0; j < 8; j++) {
            mx0 = fmaxf(mx0, fmaxf(sf[j][0], sf[j][1]));
            mx1 = fmaxf(mx1, fmaxf(sf[j][2], sf[j][3]));
        }
        #pragma unroll
        for (int off = 1; off < 4; off <<= 1) {
            mx0 = fmaxf(mx0, __shfl_xor_sync(0xffffffffu, mx0, off));
            mx1 = fmaxf(mx1, __shfl_xor_sync(0xffffffffu, mx1, off));
        }
        float nm0 = fmaxf(m0, mx0), nm1 = fmaxf(m1, mx1);
        float a0 = ex2(m0 - nm0), a1 = ex2(m1 - nm1);
        float s0 = 0.0f, s1 = 0.0f;
        #pragma unroll
        for (int j = 0; j < 8; j++) {
            sf[j][0] = ex2(sf[j][0] - nm0);
            sf[j][1] = ex2(sf[j][1] - nm0);
            sf[j][2] = ex2(sf[j][2] - nm1);
            sf[j][3] = ex2(sf[j][3] - nm1);
            s0 += sf[j][0] + sf[j][1];
            s1 += sf[j][2] + sf[j][3];
        }
        #pragma unroll
        for (int off = 1; off < 4; off <<= 1) {
            s0 += __shfl_xor_sync(0xffffffffu, s0, off);
            s1 += __shfl_xor_sync(0xffffffffu, s1, off);
        }
        m0 = nm0; m1 = nm1;
        l0 = l0 * a0 + s0;
        l1 = l1 * a1 + s1;
        #pragma unroll
        for (int j = 0; j < 8; j++) {
            of[j][0] *= a0; of[j][1] *= a0;
            of[j][2] *= a1; of[j][3] *= a1;
        }

        #pragma unroll
        for (int s = 0; s < 4; s++) {
            uint32_t pf[4];
            pf[0] = h2u(__floats2half2_rn(sf[2 * s][0],     sf[2 * s][1]));
            pf[1] = h2u(__floats2half2_rn(sf[2 * s][2],     sf[2 * s][3]));
            pf[2] = h2u(__floats2half2_rn(sf[2 * s + 1][0], sf[2 * s + 1][1]));
            pf[3] = h2u(__floats2half2_rn(sf[2 * s + 1][2], sf[2 * s + 1][3]));
            #pragma unroll
            for (int np = 0; np < 4; np++) {
                uint32_t bw[4];
                int row = 16 * s + (lane & 7) + 8 * ((lane >> 3) & 1);
                int col = 16 * np + 8 * (lane >> 4);
                ldsm_x4_t(bw[0], bw[1], bw[2], bw[3], smem_u32(&vb[row * KVS + col]));
                mma_f16(of[2 * np],     pf, &bw[0]);
                mma_f16(of[2 * np + 1], pf, &bw[2]);
            }
        }
        __syncthreads();
    }

    float inv0 = 1.0f / l0, inv1 = 1.0f / l1;
    #pragma unroll
    for (int j = 0; j < 8; j++) {
        size_t base0 = (size_t)(qrow0 + r0    ) * DMODEL + h * HDIM + 8 * j + 2 * q4;
        size_t base1 = (size_t)(qrow0 + r0 + 8) * DMODEL + h * HDIM + 8 * j + 2 * q4;
        *(__half2*)&g_attnh[base0] = __floats2half2_rn(of[j][0] * inv0, of[j][1] * inv0);
        *(__half2*)&g_attnh[base1] = __floats2half2_rn(of[j][2] * inv1, of[j][3] * inv1);
    }
}

// ---------------- launch ----------------
extern "C" void kernel_launch(void* const* d_in, const int* in_sizes, int n_in,
                              void* d_out, int out_size) {
    const float* x       = (const float*)d_in[0];
    const float* cosb    = (const float*)d_in[1];
    const float* sinb    = (const float*)d_in[2];
    const float* c       = (const float*)d_in[3];
    const float* norm1_w = (const float*)d_in[4];
    const float* Wqkv    = (const float*)d_in[5];
    const float* Wout    = (const float*)d_in[6];
    const float* q_norm_w = (const float*)d_in[7];
    const float* k_norm_w = (const float*)d_in[8];
    const float* norm2_w = (const float*)d_in[9];
    const float* W1      = (const float*)d_in[10];
    const float* b1      = (const float*)d_in[11];
    const float* W2      = (const float*)d_in[12];
    const float* b2      = (const float*)d_in[13];
    const float* ada_W   = (const float*)d_in[14];
    const float* ada_b   = (const float*)d_in[15];
    float* out = (float*)d_out;

    float *p_mod, *p_x2;
    __half *p_xnh, *p_qkvh, *p_attnh, *p_hh, *p_wqkvh, *p_wouth, *p_w1h, *p_w2h;
    cudaGetSymbolAddress((void**)&p_mod, g_mod);
    cudaGetSymbolAddress((void**)&p_x2, g_x2);
    cudaGetSymbolAddress((void**)&p_xnh, g_xnh);
    cudaGetSymbolAddress((void**)&p_qkvh, g_qkvh);
    cudaGetSymbolAddress((void**)&p_attnh, g_attnh);
    cudaGetSymbolAddress((void**)&p_hh, g_hh);
    cudaGetSymbolAddress((void**)&p_wqkvh, g_wqkvh);
    cudaGetSymbolAddress((void**)&p_wouth, g_wouth);
    cudaGetSymbolAddress((void**)&p_w1h, g_w1h);
    cudaGetSymbolAddress((void**)&p_w2h, g_w2h);

    cudaFuncSetAttribute(attn_kernel, cudaFuncAttributeMaxDynamicSharedMemorySize, ATTN_SMEM);

    // 0) all weights -> half (single launch)
    cvth_all_kernel<<<R3 / 256, 256>>>(Wqkv, Wout, W1, W2);
    // 1) adaLN modulation vectors
    mod_kernel<<<dim3(MODW / 256, BATCH), 256>>>(c, ada_W, ada_b);
    // 2) LN1 + modulate -> half
    ln_mod_kernel<<<NROWS, 256>>>(x, norm1_w, 0, 1024, p_xnh);
    // 3) qkv = xn @ Wqkv -> half
    mma_gemm_h<0><<<dim3(3 * DMODEL / 128, NROWS / 128), 128>>>(
        p_xnh, p_wqkvh, p_qkvh, NROWS, 3 * DMODEL, DMODEL, nullptr, nullptr, nullptr);
    // 4) rmsnorm + rope (q pre-scaled)
    rope_kernel<<<NROWS, 1024>>>(q_norm_w, k_norm_w, cosb, sinb);
    // 5) attention -> half
    attn_kernel<<<dim3(SEQ / 64, NHEADS, BATCH), 128, ATTN_SMEM>>>();
    // 6) x2 = x + g_msa * (attn @ Wout)   (fp32 out)
    mma_gemm_h<1><<<dim3(DMODEL / 128, NROWS / 128), 128>>>(
        p_attnh, p_wouth, p_x2, NROWS, DMODEL, DMODEL, x, nullptr, p_mod + 2 * 1024);
    // 7) LN2 + modulate -> half
    ln_mod_kernel<<<NROWS, 256>>>(p_x2, norm2_w, 3 * 1024, 4 * 1024, p_xnh);
    // 8) h = gelu(xn @ W1 + b1) -> half
    mma_gemm_h<2><<<dim3(DFF / 128, NROWS / 128), 128>>>(
        p_xnh, p_w1h, p_hh, NROWS, DFF, DMODEL, nullptr, b1, nullptr);
    // 9) out = x2 + g_mlp * (h @ W2 + b2)  (fp32 out)
    mma_gemm_h<3><<<dim3(DMODEL / 128, NROWS / 128), 128>>>(
        p_hh, p_w2h, out, NROWS, DMODEL, DFF, p_x2, b2, p_mod + 5 * 1024);
}

// round 16
// speedup vs baseline: 1.0468x; 1.0468x over previous
#include <cuda_runtime.h>
#include <cuda_fp16.h>
#include <math.h>
#include <stdint.h>

#define DMODEL 1024
#define SEQ    2048
#define BATCH  4
#define NHEADS 16
#define HDIM   64
#define DFF    4096
#define NROWS  8192
#define MODW   6144

// ---------------- scratch ----------------
__device__ float  g_mod[BATCH * MODW];
__device__ float  g_x2[(size_t)NROWS * DMODEL];
__device__ __half g_xnh[(size_t)NROWS * DMODEL];
__device__ __half g_qkvh[(size_t)NROWS * 3 * DMODEL];
__device__ __half g_attnh[(size_t)NROWS * DMODEL];
__device__ __half g_hh[(size_t)NROWS * DFF];
__device__ __half g_wqkvh[(size_t)DMODEL * 3 * DMODEL];
__device__ __half g_wouth[(size_t)DMODEL * DMODEL];
__device__ __half g_w1h[(size_t)DMODEL * DFF];
__device__ __half g_w2h[(size_t)DFF * DMODEL];

// ---------------- helpers ----------------
__device__ __forceinline__ float gelu_tanh(float x) {
    float x3 = x * x * x;
    float u = 0.7978845608028654f * (x + 0.044715f * x3);
    return 0.5f * x * (1.0f + tanhf(u));
}
__device__ __forceinline__ float ex2(float x) {
    float r; asm("ex2.approx.ftz.f32 %0, %1;" : "=f"(r) : "f"(x)); return r;
}
__device__ __forceinline__ uint32_t h2u(__half2 h) { return *(uint32_t*)&h; }
__device__ __forceinline__ uint32_t smem_u32(const void* p) {
    uint32_t a;
    asm("{ .reg .u64 t; cvta.to.shared.u64 t, %1; cvt.u32.u64 %0, t; }" : "=r"(a) : "l"(p));
    return a;
}
__device__ __forceinline__ void cpa16(uint32_t dst, const void* src) {
    asm volatile("cp.async.cg.shared.global [%0], [%1], 16;" :: "r"(dst), "l"(src) : "memory");
}
#define CP_COMMIT() asm volatile("cp.async.commit_group;" ::: "memory")
#define CP_WAIT(n)  asm volatile("cp.async.wait_group %0;" :: "n"(n) : "memory")

__device__ __forceinline__ void mma_f16(float c[4], const uint32_t a[4], const uint32_t b[2]) {
    asm volatile(
        "mma.sync.aligned.m16n8k16.row.col.f32.f16.f16.f32 "
        "{%0,%1,%2,%3}, {%4,%5,%6,%7}, {%8,%9}, {%0,%1,%2,%3};\n"
        : "+f"(c[0]), "+f"(c[1]), "+f"(c[2]), "+f"(c[3])
        : "r"(a[0]), "r"(a[1]), "r"(a[2]), "r"(a[3]), "r"(b[0]), "r"(b[1]));
}
__device__ __forceinline__ void ldsm_x4(uint32_t& r0, uint32_t& r1, uint32_t& r2, uint32_t& r3, uint32_t addr) {
    asm volatile("ldmatrix.sync.aligned.m8n8.x4.shared.b16 {%0,%1,%2,%3}, [%4];"
                 : "=r"(r0), "=r"(r1), "=r"(r2), "=r"(r3) : "r"(addr));
}
__device__ __forceinline__ void ldsm_x4_t(uint32_t& r0, uint32_t& r1, uint32_t& r2, uint32_t& r3, uint32_t addr) {
    asm volatile("ldmatrix.sync.aligned.m8n8.x4.trans.shared.b16 {%0,%1,%2,%3}, [%4];"
                 : "=r"(r0), "=r"(r1), "=r"(r2), "=r"(r3) : "r"(addr));
}

__device__ __forceinline__ void blockReduce2(float& a, float& b) {
    #pragma unroll
    for (int off = 16; off; off >>= 1) {
        a += __shfl_xor_sync(0xffffffffu, a, off);
        b += __shfl_xor_sync(0xffffffffu, b, off);
    }
    __shared__ float sa[8], sb[8];
    int w = threadIdx.x >> 5, l = threadIdx.x & 31;
    if (l == 0) { sa[w] = a; sb[w] = b; }
    __syncthreads();
    if (w == 0) {
        a = (l < 8) ? sa[l] : 0.0f;
        b = (l < 8) ? sb[l] : 0.0f;
        #pragma unroll
        for (int off = 4; off; off >>= 1) {
            a += __shfl_xor_sync(0xffffffffu, a, off);
            b += __shfl_xor_sync(0xffffffffu, b, off);
        }
        if (l == 0) { sa[0] = a; sb[0] = b; }
    }
    __syncthreads();
    a = sa[0]; b = sb[0];
}

// ---------------- 0) all four weights fp32 -> fp16 in one launch ----------------
#define R0 786432
#define R1 (R0 + 262144)
#define R2 (R1 + 1048576)
#define R3 (R2 + 1048576)
__global__ void cvth_all_kernel(const float* __restrict__ wqkv, const float* __restrict__ wout,
                                const float* __restrict__ w1, const float* __restrict__ w2) {
    int i = blockIdx.x * 256 + threadIdx.x;
    const float* in;
    __half* out;
    int j;
    if (i < R0)      { in = wqkv; out = g_wqkvh; j = i; }
    else if (i < R1) { in = wout; out = g_wouth; j = i - R0; }
    else if (i < R2) { in = w1;   out = g_w1h;   j = i - R1; }
    else             { in = w2;   out = g_w2h;   j = i - R2; }
    float4 v = ((const float4*)in)[j];
    __half2 lo = __floats2half2_rn(v.x, v.y);
    __half2 hi = __floats2half2_rn(v.z, v.w);
    ((uint2*)out)[j] = make_uint2(h2u(lo), h2u(hi));
}

// ---------------- 1) mod = c @ ada_W + ada_b ----------------
__global__ void mod_kernel(const float* __restrict__ c, const float* __restrict__ W,
                           const float* __restrict__ bias) {
    __shared__ float cs[1024];
    int b = blockIdx.y;
    int col = blockIdx.x * 256 + threadIdx.x;
    for (int i = threadIdx.x; i < 1024; i += 256) cs[i] = c[b * 1024 + i];
    __syncthreads();
    float acc = 0.0f;
    #pragma unroll 4
    for (int k = 0; k < 1024; k++) acc += cs[k] * W[(size_t)k * MODW + col];
    g_mod[b * MODW + col] = acc + bias[col];
}

// ---------------- 2) layernorm + modulate -> half ----------------
__global__ void ln_mod_kernel(const float* __restrict__ X, const float* __restrict__ w,
                              int shOff, int scOff, __half* __restrict__ out) {
    int row = blockIdx.x;
    int b = row >> 11;
    const float4* xr = (const float4*)(X + (size_t)row * DMODEL);
    float4 v = xr[threadIdx.x];
    float s = v.x + v.y + v.z + v.w;
    float ss = v.x * v.x + v.y * v.y + v.z * v.z + v.w * v.w;
    blockReduce2(s, ss);
    float mu = s * (1.0f / 1024.0f);
    float var = ss * (1.0f / 1024.0f) - mu * mu;
    float r = rsqrtf(var + 1e-5f);
    int d = threadIdx.x * 4;
    const float* mb = g_mod + b * MODW;
    float o0 = (v.x - mu) * r * w[d + 0] * (1.0f + mb[scOff + d + 0]) + mb[shOff + d + 0];
    float o1 = (v.y - mu) * r * w[d + 1] * (1.0f + mb[scOff + d + 1]) + mb[shOff + d + 1];
    float o2 = (v.z - mu) * r * w[d + 2] * (1.0f + mb[scOff + d + 2]) + mb[shOff + d + 2];
    float o3 = (v.w - mu) * r * w[d + 3] * (1.0f + mb[scOff + d + 3]) + mb[shOff + d + 3];
    ((uint2*)(out + (size_t)row * DMODEL))[threadIdx.x] =
        make_uint2(h2u(__floats2half2_rn(o0, o1)), h2u(__floats2half2_rn(o2, o3)));
}

// ---------------- 3) FP16 HMMA GEMM, 128x128x32, 2-stage cp.async (R8-exact) --------
// MODE 0: Ch = acc (half)        MODE 1: Cf = res + gate * acc
// MODE 2: Ch = gelu(acc + bias)  MODE 3: Cf = res + gate * (acc + bias)
#define AH_STRIDE 40
#define BH_STRIDE 136

template<int MODE>
__global__ void __launch_bounds__(256, 2)
mma_gemm_h(const __half* __restrict__ A, const __half* __restrict__ B, void* __restrict__ Cp,
           int M, int N, int K,
           const float* __restrict__ res, const float* __restrict__ bias,
           const float* __restrict__ gate) {
    __shared__ __half As[2][128 * AH_STRIDE];
    __shared__ __half Bs[2][32 * BH_STRIDE];
    const int t = threadIdx.x;
    const int lane = t & 31, wid = t >> 5;
    const int warp_m = wid & 1, warp_n = wid >> 1;
    const int rowBase = blockIdx.y * 128, colBase = blockIdx.x * 128;
    const int nk = K >> 5;

    float acc[4][4][4];
    #pragma unroll
    for (int mt = 0; mt < 4; mt++)
        #pragma unroll
        for (int nt = 0; nt < 4; nt++)
            #pragma unroll
            for (int f = 0; f < 4; f++) acc[mt][nt][f] = 0.0f;

    auto load_stage = [&](int kt, int buf) {
        #pragma unroll
        for (int i = 0; i < 2; i++) {
            int idx = t + i * 256;
            int r = idx >> 2, q = idx & 3;
            cpa16(smem_u32(&As[buf][r * AH_STRIDE + q * 8]),
                  A + (size_t)(rowBase + r) * K + kt * 32 + q * 8);
        }
        #pragma unroll
        for (int i = 0; i < 2; i++) {
            int idx = t + i * 256;
            int k = idx >> 4, cq = idx & 15;
            cpa16(smem_u32(&Bs[buf][k * BH_STRIDE + cq * 8]),
                  B + (size_t)(kt * 32 + k) * N + colBase + cq * 8);
        }
        CP_COMMIT();
    };

    load_stage(0, 0);
    for (int kt = 0; kt < nk; kt++) {
        if (kt + 1 < nk) {
            load_stage(kt + 1, (kt + 1) & 1);
            CP_WAIT(1);
        } else {
            CP_WAIT(0);
        }
        __syncthreads();
        const __half* as = As[kt & 1];
        const __half* bs = Bs[kt & 1];
        #pragma unroll
        for (int ks = 0; ks < 2; ks++) {
            uint32_t af[4][4], bw[2][4];
            #pragma unroll
            for (int mt = 0; mt < 4; mt++) {
                int row = warp_m * 64 + mt * 16 + (lane & 15);
                int col = ks * 16 + 8 * (lane >> 4);
                ldsm_x4(af[mt][0], af[mt][1], af[mt][2], af[mt][3],
                        smem_u32(&as[row * AH_STRIDE + col]));
            }
            #pragma unroll
            for (int np = 0; np < 2; np++) {
                int row = ks * 16 + (lane & 7) + 8 * ((lane >> 3) & 1);
                int col = warp_n * 32 + np * 16 + 8 * (lane >> 4);
                ldsm_x4_t(bw[np][0], bw[np][1], bw[np][2], bw[np][3],
                          smem_u32(&bs[row * BH_STRIDE + col]));
            }
            #pragma unroll
            for (int mt = 0; mt < 4; mt++)
                #pragma unroll
                for (int nt = 0; nt < 4; nt++)
                    mma_f16(acc[mt][nt], af[mt], &bw[nt >> 1][(nt & 1) * 2]);
        }
        __syncthreads();
    }

    #pragma unroll
    for (int mt = 0; mt < 4; mt++) {
        #pragma unroll
        for (int nt = 0; nt < 4; nt++) {
            #pragma unroll
            for (int half_ = 0; half_ < 2; half_++) {
                int gr = rowBase + warp_m * 64 + mt * 16 + (lane >> 2) + half_ * 8;
                int gc = colBase + warp_n * 32 + nt * 8 + (lane & 3) * 2;
                int bb = gr >> 11;
                size_t off = (size_t)gr * N + gc;
                float v0 = acc[mt][nt][half_ * 2 + 0];
                float v1 = acc[mt][nt][half_ * 2 + 1];
                if (MODE == 0) {
                    *(__half2*)((__half*)Cp + off) = __floats2half2_rn(v0, v1);
                } else if (MODE == 1) {
                    float* Cf = (float*)Cp;
                    Cf[off]     = res[off]     + gate[bb * MODW + gc]     * v0;
                    Cf[off + 1] = res[off + 1] + gate[bb * MODW + gc + 1] * v1;
                } else if (MODE == 2) {
                    *(__half2*)((__half*)Cp + off) =
                        __floats2half2_rn(gelu_tanh(v0 + bias[gc]), gelu_tanh(v1 + bias[gc + 1]));
                } else {
                    float* Cf = (float*)Cp;
                    Cf[off]     = res[off]     + gate[bb * MODW + gc]     * (v0 + bias[gc]);
                    Cf[off + 1] = res[off + 1] + gate[bb * MODW + gc + 1] * (v1 + bias[gc + 1]);
                }
            }
        }
    }
}

// ---------------- 4) rmsnorm + rope, warp-per-head, no smem / no syncthreads ---------
// 512 threads/row: warp = head; lane owns dims (2*lane, 2*lane+1); q pre-scaled.
__global__ void __launch_bounds__(512)
rope_kernel(const float* __restrict__ qw, const float* __restrict__ kw,
            const float* __restrict__ cosb, const float* __restrict__ sinb) {
    int row = blockIdx.x;
    int s = row & (SEQ - 1);
    int t = threadIdx.x;
    int h = t >> 5, lane = t & 31;
    const float lscale = 0.125f * 1.4426950408889634f;

    float2 cs2 = ((const float2*)(cosb + (size_t)s * HDIM))[lane];
    float2 sn2 = ((const float2*)(sinb + (size_t)s * HDIM))[lane];
    float sign = (lane < 16) ? -1.0f : 1.0f;

    #pragma unroll
    for (int which = 0; which < 2; which++) {
        size_t base = ((size_t)row * 3 + which) * DMODEL + h * HDIM;
        __half2 v2 = *(const __half2*)(g_qkvh + base + 2 * lane);
        float v0 = __half2float(__low2half(v2));
        float v1 = __half2float(__high2half(v2));
        float ss = v0 * v0 + v1 * v1;
        #pragma unroll
        for (int off = 16; off; off >>= 1) ss += __shfl_xor_sync(0xffffffffu, ss, off);
        float r = rsqrtf(ss * (1.0f / 64.0f) + 1e-6f);
        const float* ww = which ? kw : qw;
        float xn0 = v0 * r * ww[2 * lane];
        float xn1 = v1 * r * ww[2 * lane + 1];
        // rotate_half partner: dims 2*lane±32 live in lane^16
        float p0 = __shfl_xor_sync(0xffffffffu, xn0, 16);
        float p1 = __shfl_xor_sync(0xffffffffu, xn1, 16);
        float rot0 = sign * p0, rot1 = sign * p1;
        float o0 = xn0 * cs2.x + rot0 * sn2.x;
        float o1 = xn1 * cs2.y + rot1 * sn2.y;
        if (which == 0) { o0 *= lscale; o1 *= lscale; }
        *(__half2*)(g_qkvh + base + 2 * lane) = __floats2half2_rn(o0, o1);
    }
}

// ---------------- 5) flash attention, fp16 HMMA (R8-exact) ----------------
#define KVS 72
#define ATTN_SMEM (2 * 2 * 64 * KVS * 2)

__global__ void __launch_bounds__(128)
attn_kernel() {
    extern __shared__ __half smemh[];
    __half* ksm = smemh;
    __half* vsm = smemh + 2 * 64 * KVS;

    const int qt = blockIdx.x, h = blockIdx.y, b = blockIdx.z;
    const int t = threadIdx.x;
    const int lane = t & 31, w = t >> 5;
    const int r0 = lane >> 2, q4 = lane & 3;

    const size_t kbase = ((size_t)(b * SEQ) * 3 + 1) * DMODEL + h * HDIM;
    const size_t vbase = kbase + DMODEL;
    const int qrow0 = b * SEQ + qt * 64 + w * 16;
    const __half* Qh = g_qkvh + (size_t)qrow0 * 3 * DMODEL + h * HDIM;

    uint32_t qf[4][4];
    #pragma unroll
    for (int s = 0; s < 4; s++) {
        int kk = 16 * s + 2 * q4;
        qf[s][0] = *(const uint32_t*)(Qh + (size_t)(r0    ) * 3072 + kk    );
        qf[s][1] = *(const uint32_t*)(Qh + (size_t)(r0 + 8) * 3072 + kk    );
        qf[s][2] = *(const uint32_t*)(Qh + (size_t)(r0    ) * 3072 + kk + 8);
        qf[s][3] = *(const uint32_t*)(Qh + (size_t)(r0 + 8) * 3072 + kk + 8);
    }

    float of[8][4];
    #pragma unroll
    for (int j = 0; j < 8; j++)
        #pragma unroll
        for (int f = 0; f < 4; f++) of[j][f] = 0.0f;
    float m0 = -1e30f, m1 = -1e30f, l0 = 0.0f, l1 = 0.0f;

    auto loadKV = [&](int k0, int buf) {
        #pragma unroll
        for (int i = 0; i < 4; i++) {
            int idx = t + i * 128;
            int row = idx >> 3, c = idx & 7;
            cpa16(smem_u32(&ksm[buf * 64 * KVS + row * KVS + c * 8]),
                  g_qkvh + kbase + (size_t)(k0 + row) * 3072 + c * 8);
            cpa16(smem_u32(&vsm[buf * 64 * KVS + row * KVS + c * 8]),
                  g_qkvh + vbase + (size_t)(k0 + row) * 3072 + c * 8);
        }
        CP_COMMIT();
    };

    loadKV(0, 0);
    for (int kt = 0; kt < SEQ / 64; kt++) {
        if (kt + 1 < SEQ / 64) {
            loadKV((kt + 1) * 64, (kt + 1) & 1);
            CP_WAIT(1);
        } else {
            CP_WAIT(0);
        }
        __syncthreads();
        const __half* kb = ksm + (kt & 1) * 64 * KVS;
        const __half* vb = vsm + (kt & 1) * 64 * KVS;

        float sf[8][4];
        #pragma unroll
        for (int j = 0; j < 8; j++)
            #pragma unroll
            for (int f = 0; f < 4; f++) sf[j][f] = 0.0f;
        #pragma unroll
        for (int s = 0; s < 4; s++) {
            #pragma unroll
            for (int np = 0; np < 4; np++) {
                uint32_t bw[4];
                int row = 16 * np + (lane & 7) + 8 * (lane >> 4);
                int col = 16 * s + 8 * ((lane >> 3) & 1);
                ldsm_x4(bw[0], bw[1], bw[2], bw[3], smem_u32(&kb[row * KVS + col]));
                mma_f16(sf[2 * np],     qf[s], &bw[0]);
                mma_f16(sf[2 * np + 1], qf[s], &bw[2]);
            }
        }

        float mx0 = -1e30f, mx1 = -1e30f;
        #pragma unroll
        for (int j = 0; j < 8; j++) {
            mx0 = fmaxf(mx0, fmaxf(sf[j][0], sf[j][1]));
            mx1 = fmaxf(mx1, fmaxf(sf[j][2], sf[j][3]));
        }
        #pragma unroll
        for (int off = 1; off < 4; off <<= 1) {
            mx0 = fmaxf(mx0, __shfl_xor_sync(0xffffffffu, mx0, off));
            mx1 = fmaxf(mx1, __shfl_xor_sync(0xffffffffu, mx1, off));
        }
        float nm0 = fmaxf(m0, mx0), nm1 = fmaxf(m1, mx1);
        float a0 = ex2(m0 - nm0), a1 = ex2(m1 - nm1);
        float s0 = 0.0f, s1 = 0.0f;
        #pragma unroll
        for (int j = 0; j < 8; j++) {
            sf[j][0] = ex2(sf[j][0] - nm0);
            sf[j][1] = ex2(sf[j][1] - nm0);
            sf[j][2] = ex2(sf[j][2] - nm1);
            sf[j][3] = ex2(sf[j][3] - nm1);
            s0 += sf[j][0] + sf[j][1];
            s1 += sf[j][2] + sf[j][3];
        }
        #pragma unroll
        for (int off = 1; off < 4; off <<= 1) {
            s0 += __shfl_xor_sync(0xffffffffu, s0, off);
            s1 += __shfl_xor_sync(0xffffffffu, s1, off);
        }
        m0 = nm0; m1 = nm1;
        l0 = l0 * a0 + s0;
        l1 = l1 * a1 + s1;
        #pragma unroll
        for (int j = 0; j < 8; j++) {
            of[j][0] *= a0; of[j][1] *= a0;
            of[j][2] *= a1; of[j][3] *= a1;
        }

        #pragma unroll
        for (int s = 0; s < 4; s++) {
            uint32_t pf[4];
            pf[0] = h2u(__floats2half2_rn(sf[2 * s][0],     sf[2 * s][1]));
            pf[1] = h2u(__floats2half2_rn(sf[2 * s][2],     sf[2 * s][3]));
            pf[2] = h2u(__floats2half2_rn(sf[2 * s + 1][0], sf[2 * s + 1][1]));
            pf[3] = h2u(__floats2half2_rn(sf[2 * s + 1][2], sf[2 * s + 1][3]));
            #pragma unroll
            for (int np = 0; np < 4; np++) {
                uint32_t bw[4];
                int row = 16 * s + (lane & 7) + 8 * ((lane >> 3) & 1);
                int col = 16 * np + 8 * (lane >> 4);
                ldsm_x4_t(bw[0], bw[1], bw[2], bw[3], smem_u32(&vb[row * KVS + col]));
                mma_f16(of[2 * np],     pf, &bw[0]);
                mma_f16(of[2 * np + 1], pf, &bw[2]);
            }
        }
        __syncthreads();
    }

    float inv0 = 1.0f / l0, inv1 = 1.0f / l1;
    #pragma unroll
    for (int j = 0; j < 8; j++) {
        size_t base0 = (size_t)(qrow0 + r0    ) * DMODEL + h * HDIM + 8 * j + 2 * q4;
        size_t base1 = (size_t)(qrow0 + r0 + 8) * DMODEL + h * HDIM + 8 * j + 2 * q4;
        *(__half2*)&g_attnh[base0] = __floats2half2_rn(of[j][0] * inv0, of[j][1] * inv0);
        *(__half2*)&g_attnh[base1] = __floats2half2_rn(of[j][2] * inv1, of[j][3] * inv1);
    }
}

// ---------------- launch ----------------
extern "C" void kernel_launch(void* const* d_in, const int* in_sizes, int n_in,
                              void* d_out, int out_size) {
    const float* x       = (const float*)d_in[0];
    const float* cosb    = (const float*)d_in[1];
    const float* sinb    = (const float*)d_in[2];
    const float* c       = (const float*)d_in[3];
    const float* norm1_w = (const float*)d_in[4];
    const float* Wqkv    = (const float*)d_in[5];
    const float* Wout    = (const float*)d_in[6];
    const float* q_norm_w = (const float*)d_in[7];
    const float* k_norm_w = (const float*)d_in[8];
    const float* norm2_w = (const float*)d_in[9];
    const float* W1      = (const float*)d_in[10];
    const float* b1      = (const float*)d_in[11];
    const float* W2      = (const float*)d_in[12];
    const float* b2      = (const float*)d_in[13];
    const float* ada_W   = (const float*)d_in[14];
    const float* ada_b   = (const float*)d_in[15];
    float* out = (float*)d_out;

    float *p_mod, *p_x2;
    __half *p_xnh, *p_qkvh, *p_attnh, *p_hh, *p_wqkvh, *p_wouth, *p_w1h, *p_w2h;
    cudaGetSymbolAddress((void**)&p_mod, g_mod);
    cudaGetSymbolAddress((void**)&p_x2, g_x2);
    cudaGetSymbolAddress((void**)&p_xnh, g_xnh);
    cudaGetSymbolAddress((void**)&p_qkvh, g_qkvh);
    cudaGetSymbolAddress((void**)&p_attnh, g_attnh);
    cudaGetSymbolAddress((void**)&p_hh, g_hh);
    cudaGetSymbolAddress((void**)&p_wqkvh, g_wqkvh);
    cudaGetSymbolAddress((void**)&p_wouth, g_wouth);
    cudaGetSymbolAddress((void**)&p_w1h, g_w1h);
    cudaGetSymbolAddress((void**)&p_w2h, g_w2h);

    cudaFuncSetAttribute(attn_kernel, cudaFuncAttributeMaxDynamicSharedMemorySize, ATTN_SMEM);

    // 0) all weights -> half (single launch)
    cvth_all_kernel<<<R3 / 256, 256>>>(Wqkv, Wout, W1, W2);
    // 1) adaLN modulation vectors
    mod_kernel<<<dim3(MODW / 256, BATCH), 256>>>(c, ada_W, ada_b);
    // 2) LN1 + modulate -> half
    ln_mod_kernel<<<NROWS, 256>>>(x, norm1_w, 0, 1024, p_xnh);
    // 3) qkv = xn @ Wqkv -> half
    mma_gemm_h<0><<<dim3(3 * DMODEL / 128, NROWS / 128), 256>>>(
        p_xnh, p_wqkvh, p_qkvh, NROWS, 3 * DMODEL, DMODEL, nullptr, nullptr, nullptr);
    // 4) rmsnorm + rope (warp-per-head, q pre-scaled)
    rope_kernel<<<NROWS, 512>>>(q_norm_w, k_norm_w, cosb, sinb);
    // 5) attention -> half
    attn_kernel<<<dim3(SEQ / 64, NHEADS, BATCH), 128, ATTN_SMEM>>>();
    // 6) x2 = x + g_msa * (attn @ Wout)   (fp32 out)
    mma_gemm_h<1><<<dim3(DMODEL / 128, NROWS / 128), 256>>>(
        p_attnh, p_wouth, p_x2, NROWS, DMODEL, DMODEL, x, nullptr, p_mod + 2 * 1024);
    // 7) LN2 + modulate -> half
    ln_mod_kernel<<<NROWS, 256>>>(p_x2, norm2_w, 3 * 1024, 4 * 1024, p_xnh);
    // 8) h = gelu(xn @ W1 + b1) -> half
    mma_gemm_h<2><<<dim3(DFF / 128, NROWS / 128), 256>>>(
        p_xnh, p_w1h, p_hh, NROWS, DFF, DMODEL, nullptr, b1, nullptr);
    // 9) out = x2 + g_mlp * (h @ W2 + b2)  (fp32 out)
    mma_gemm_h<3><<<dim3(DMODEL / 128, NROWS / 128), 256>>>(
        p_hh, p_w2h, out, NROWS, DMODEL, DFF, p_x2, b2, p_mod + 5 * 1024);
}

// round 17
// speedup vs baseline: 1.0557x; 1.0085x over previous
#include <cuda_runtime.h>
#include <cuda_fp16.h>
#include <math.h>
#include <stdint.h>

#define DMODEL 1024
#define SEQ    2048
#define BATCH  4
#define NHEADS 16
#define HDIM   64
#define DFF    4096
#define NROWS  8192
#define MODW   6144

// ---------------- scratch ----------------
__device__ float  g_mod[BATCH * MODW];
__device__ float  g_x2[(size_t)NROWS * DMODEL];
__device__ __half g_xnh[(size_t)NROWS * DMODEL];
__device__ __half g_qkvh[(size_t)NROWS * 3 * DMODEL];
__device__ __half g_attnh[(size_t)NROWS * DMODEL];
__device__ __half g_hh[(size_t)NROWS * DFF];
__device__ __half g_wqkvh[(size_t)DMODEL * 3 * DMODEL];
__device__ __half g_wouth[(size_t)DMODEL * DMODEL];
__device__ __half g_w1h[(size_t)DMODEL * DFF];
__device__ __half g_w2h[(size_t)DFF * DMODEL];

// ---------------- helpers ----------------
__device__ __forceinline__ float gelu_tanh(float x) {
    float x3 = x * x * x;
    float u = 0.7978845608028654f * (x + 0.044715f * x3);
    return 0.5f * x * (1.0f + tanhf(u));
}
__device__ __forceinline__ float ex2(float x) {
    float r; asm("ex2.approx.ftz.f32 %0, %1;" : "=f"(r) : "f"(x)); return r;
}
__device__ __forceinline__ uint32_t h2u(__half2 h) { return *(uint32_t*)&h; }
__device__ __forceinline__ uint32_t smem_u32(const void* p) {
    uint32_t a;
    asm("{ .reg .u64 t; cvta.to.shared.u64 t, %1; cvt.u32.u64 %0, t; }" : "=r"(a) : "l"(p));
    return a;
}
__device__ __forceinline__ void cpa16(uint32_t dst, const void* src) {
    asm volatile("cp.async.cg.shared.global [%0], [%1], 16;" :: "r"(dst), "l"(src) : "memory");
}
#define CP_COMMIT() asm volatile("cp.async.commit_group;" ::: "memory")
#define CP_WAIT(n)  asm volatile("cp.async.wait_group %0;" :: "n"(n) : "memory")

__device__ __forceinline__ void mma_f16(float c[4], const uint32_t a[4], const uint32_t b[2]) {
    asm volatile(
        "mma.sync.aligned.m16n8k16.row.col.f32.f16.f16.f32 "
        "{%0,%1,%2,%3}, {%4,%5,%6,%7}, {%8,%9}, {%0,%1,%2,%3};\n"
        : "+f"(c[0]), "+f"(c[1]), "+f"(c[2]), "+f"(c[3])
        : "r"(a[0]), "r"(a[1]), "r"(a[2]), "r"(a[3]), "r"(b[0]), "r"(b[1]));
}
__device__ __forceinline__ void ldsm_x4(uint32_t& r0, uint32_t& r1, uint32_t& r2, uint32_t& r3, uint32_t addr) {
    asm volatile("ldmatrix.sync.aligned.m8n8.x4.shared.b16 {%0,%1,%2,%3}, [%4];"
                 : "=r"(r0), "=r"(r1), "=r"(r2), "=r"(r3) : "r"(addr));
}
__device__ __forceinline__ void ldsm_x4_t(uint32_t& r0, uint32_t& r1, uint32_t& r2, uint32_t& r3, uint32_t addr) {
    asm volatile("ldmatrix.sync.aligned.m8n8.x4.trans.shared.b16 {%0,%1,%2,%3}, [%4];"
                 : "=r"(r0), "=r"(r1), "=r"(r2), "=r"(r3) : "r"(addr));
}

__device__ __forceinline__ void blockReduce2(float& a, float& b) {
    #pragma unroll
    for (int off = 16; off; off >>= 1) {
        a += __shfl_xor_sync(0xffffffffu, a, off);
        b += __shfl_xor_sync(0xffffffffu, b, off);
    }
    __shared__ float sa[8], sb[8];
    int w = threadIdx.x >> 5, l = threadIdx.x & 31;
    if (l == 0) { sa[w] = a; sb[w] = b; }
    __syncthreads();
    if (w == 0) {
        a = (l < 8) ? sa[l] : 0.0f;
        b = (l < 8) ? sb[l] : 0.0f;
        #pragma unroll
        for (int off = 4; off; off >>= 1) {
            a += __shfl_xor_sync(0xffffffffu, a, off);
            b += __shfl_xor_sync(0xffffffffu, b, off);
        }
        if (l == 0) { sa[0] = a; sb[0] = b; }
    }
    __syncthreads();
    a = sa[0]; b = sb[0];
}

// ---------------- 0) all four weights fp32 -> fp16 in one launch ----------------
#define R0 786432
#define R1 (R0 + 262144)
#define R2 (R1 + 1048576)
#define R3 (R2 + 1048576)
__global__ void cvth_all_kernel(const float* __restrict__ wqkv, const float* __restrict__ wout,
                                const float* __restrict__ w1, const float* __restrict__ w2) {
    int i = blockIdx.x * 256 + threadIdx.x;
    const float* in;
    __half* out;
    int j;
    if (i < R0)      { in = wqkv; out = g_wqkvh; j = i; }
    else if (i < R1) { in = wout; out = g_wouth; j = i - R0; }
    else if (i < R2) { in = w1;   out = g_w1h;   j = i - R1; }
    else             { in = w2;   out = g_w2h;   j = i - R2; }
    float4 v = ((const float4*)in)[j];
    __half2 lo = __floats2half2_rn(v.x, v.y);
    __half2 hi = __floats2half2_rn(v.z, v.w);
    ((uint2*)out)[j] = make_uint2(h2u(lo), h2u(hi));
}

// ---------------- 1) mod = c @ ada_W + ada_b ----------------
__global__ void mod_kernel(const float* __restrict__ c, const float* __restrict__ W,
                           const float* __restrict__ bias) {
    __shared__ float cs[1024];
    int b = blockIdx.y;
    int col = blockIdx.x * 256 + threadIdx.x;
    for (int i = threadIdx.x; i < 1024; i += 256) cs[i] = c[b * 1024 + i];
    __syncthreads();
    float acc = 0.0f;
    #pragma unroll 4
    for (int k = 0; k < 1024; k++) acc += cs[k] * W[(size_t)k * MODW + col];
    g_mod[b * MODW + col] = acc + bias[col];
}

// ---------------- 2) layernorm + modulate -> half ----------------
__global__ void ln_mod_kernel(const float* __restrict__ X, const float* __restrict__ w,
                              int shOff, int scOff, __half* __restrict__ out) {
    int row = blockIdx.x;
    int b = row >> 11;
    const float4* xr = (const float4*)(X + (size_t)row * DMODEL);
    float4 v = xr[threadIdx.x];
    float s = v.x + v.y + v.z + v.w;
    float ss = v.x * v.x + v.y * v.y + v.z * v.z + v.w * v.w;
    blockReduce2(s, ss);
    float mu = s * (1.0f / 1024.0f);
    float var = ss * (1.0f / 1024.0f) - mu * mu;
    float r = rsqrtf(var + 1e-5f);
    int d = threadIdx.x * 4;
    const float* mb = g_mod + b * MODW;
    float o0 = (v.x - mu) * r * w[d + 0] * (1.0f + mb[scOff + d + 0]) + mb[shOff + d + 0];
    float o1 = (v.y - mu) * r * w[d + 1] * (1.0f + mb[scOff + d + 1]) + mb[shOff + d + 1];
    float o2 = (v.z - mu) * r * w[d + 2] * (1.0f + mb[scOff + d + 2]) + mb[shOff + d + 2];
    float o3 = (v.w - mu) * r * w[d + 3] * (1.0f + mb[scOff + d + 3]) + mb[shOff + d + 3];
    ((uint2*)(out + (size_t)row * DMODEL))[threadIdx.x] =
        make_uint2(h2u(__floats2half2_rn(o0, o1)), h2u(__floats2half2_rn(o2, o3)));
}

// ---------------- 3) FP16 HMMA GEMM, 128x128x32, 2-stage cp.async (R8-exact) --------
// MODE 0: Ch = acc (half)        MODE 1: Cf = res + gate * acc
// MODE 2: Ch = gelu(acc + bias)  MODE 3: Cf = res + gate * (acc + bias)
#define AH_STRIDE 40
#define BH_STRIDE 136

template<int MODE>
__global__ void __launch_bounds__(256, 2)
mma_gemm_h(const __half* __restrict__ A, const __half* __restrict__ B, void* __restrict__ Cp,
           int M, int N, int K,
           const float* __restrict__ res, const float* __restrict__ bias,
           const float* __restrict__ gate) {
    __shared__ __half As[2][128 * AH_STRIDE];
    __shared__ __half Bs[2][32 * BH_STRIDE];
    const int t = threadIdx.x;
    const int lane = t & 31, wid = t >> 5;
    const int warp_m = wid & 1, warp_n = wid >> 1;
    const int rowBase = blockIdx.y * 128, colBase = blockIdx.x * 128;
    const int nk = K >> 5;

    float acc[4][4][4];
    #pragma unroll
    for (int mt = 0; mt < 4; mt++)
        #pragma unroll
        for (int nt = 0; nt < 4; nt++)
            #pragma unroll
            for (int f = 0; f < 4; f++) acc[mt][nt][f] = 0.0f;

    auto load_stage = [&](int kt, int buf) {
        #pragma unroll
        for (int i = 0; i < 2; i++) {
            int idx = t + i * 256;
            int r = idx >> 2, q = idx & 3;
            cpa16(smem_u32(&As[buf][r * AH_STRIDE + q * 8]),
                  A + (size_t)(rowBase + r) * K + kt * 32 + q * 8);
        }
        #pragma unroll
        for (int i = 0; i < 2; i++) {
            int idx = t + i * 256;
            int k = idx >> 4, cq = idx & 15;
            cpa16(smem_u32(&Bs[buf][k * BH_STRIDE + cq * 8]),
                  B + (size_t)(kt * 32 + k) * N + colBase + cq * 8);
        }
        CP_COMMIT();
    };

    load_stage(0, 0);
    for (int kt = 0; kt < nk; kt++) {
        if (kt + 1 < nk) {
            load_stage(kt + 1, (kt + 1) & 1);
            CP_WAIT(1);
        } else {
            CP_WAIT(0);
        }
        __syncthreads();
        const __half* as = As[kt & 1];
        const __half* bs = Bs[kt & 1];
        #pragma unroll
        for (int ks = 0; ks < 2; ks++) {
            uint32_t af[4][4], bw[2][4];
            #pragma unroll
            for (int mt = 0; mt < 4; mt++) {
                int row = warp_m * 64 + mt * 16 + (lane & 15);
                int col = ks * 16 + 8 * (lane >> 4);
                ldsm_x4(af[mt][0], af[mt][1], af[mt][2], af[mt][3],
                        smem_u32(&as[row * AH_STRIDE + col]));
            }
            #pragma unroll
            for (int np = 0; np < 2; np++) {
                int row = ks * 16 + (lane & 7) + 8 * ((lane >> 3) & 1);
                int col = warp_n * 32 + np * 16 + 8 * (lane >> 4);
                ldsm_x4_t(bw[np][0], bw[np][1], bw[np][2], bw[np][3],
                          smem_u32(&bs[row * BH_STRIDE + col]));
            }
            #pragma unroll
            for (int mt = 0; mt < 4; mt++)
                #pragma unroll
                for (int nt = 0; nt < 4; nt++)
                    mma_f16(acc[mt][nt], af[mt], &bw[nt >> 1][(nt & 1) * 2]);
        }
        __syncthreads();
    }

    #pragma unroll
    for (int mt = 0; mt < 4; mt++) {
        #pragma unroll
        for (int nt = 0; nt < 4; nt++) {
            #pragma unroll
            for (int half_ = 0; half_ < 2; half_++) {
                int gr = rowBase + warp_m * 64 + mt * 16 + (lane >> 2) + half_ * 8;
                int gc = colBase + warp_n * 32 + nt * 8 + (lane & 3) * 2;
                int bb = gr >> 11;
                size_t off = (size_t)gr * N + gc;
                float v0 = acc[mt][nt][half_ * 2 + 0];
                float v1 = acc[mt][nt][half_ * 2 + 1];
                if (MODE == 0) {
                    *(__half2*)((__half*)Cp + off) = __floats2half2_rn(v0, v1);
                } else if (MODE == 1) {
                    float* Cf = (float*)Cp;
                    Cf[off]     = res[off]     + gate[bb * MODW + gc]     * v0;
                    Cf[off + 1] = res[off + 1] + gate[bb * MODW + gc + 1] * v1;
                } else if (MODE == 2) {
                    *(__half2*)((__half*)Cp + off) =
                        __floats2half2_rn(gelu_tanh(v0 + bias[gc]), gelu_tanh(v1 + bias[gc + 1]));
                } else {
                    float* Cf = (float*)Cp;
                    Cf[off]     = res[off]     + gate[bb * MODW + gc]     * (v0 + bias[gc]);
                    Cf[off + 1] = res[off + 1] + gate[bb * MODW + gc + 1] * (v1 + bias[gc + 1]);
                }
            }
        }
    }
}

// ---------------- 4) rmsnorm + rope, warp-per-head, no smem / no syncthreads ---------
__global__ void __launch_bounds__(512)
rope_kernel(const float* __restrict__ qw, const float* __restrict__ kw,
            const float* __restrict__ cosb, const float* __restrict__ sinb) {
    int row = blockIdx.x;
    int s = row & (SEQ - 1);
    int t = threadIdx.x;
    int h = t >> 5, lane = t & 31;
    const float lscale = 0.125f * 1.4426950408889634f;

    float2 cs2 = ((const float2*)(cosb + (size_t)s * HDIM))[lane];
    float2 sn2 = ((const float2*)(sinb + (size_t)s * HDIM))[lane];
    float sign = (lane < 16) ? -1.0f : 1.0f;

    #pragma unroll
    for (int which = 0; which < 2; which++) {
        size_t base = ((size_t)row * 3 + which) * DMODEL + h * HDIM;
        __half2 v2 = *(const __half2*)(g_qkvh + base + 2 * lane);
        float v0 = __half2float(__low2half(v2));
        float v1 = __half2float(__high2half(v2));
        float ss = v0 * v0 + v1 * v1;
        #pragma unroll
        for (int off = 16; off; off >>= 1) ss += __shfl_xor_sync(0xffffffffu, ss, off);
        float r = rsqrtf(ss * (1.0f / 64.0f) + 1e-6f);
        const float* ww = which ? kw : qw;
        float xn0 = v0 * r * ww[2 * lane];
        float xn1 = v1 * r * ww[2 * lane + 1];
        float p0 = __shfl_xor_sync(0xffffffffu, xn0, 16);
        float p1 = __shfl_xor_sync(0xffffffffu, xn1, 16);
        float rot0 = sign * p0, rot1 = sign * p1;
        float o0 = xn0 * cs2.x + rot0 * sn2.x;
        float o1 = xn1 * cs2.y + rot1 * sn2.y;
        if (which == 0) { o0 *= lscale; o1 *= lscale; }
        *(__half2*)(g_qkvh + base + 2 * lane) = __floats2half2_rn(o0, o1);
    }
}

// ---------------- 5) flash attention, fp16 HMMA, FIXED-MAX softmax ----------------
// Softmax shift-invariance + bounded logits (|s*log2e/8| <~ 12) => skip running max,
// no O-rescale, lane-local l accumulation reduced once after the loop.
#define KVS 72
#define ATTN_SMEM (2 * 2 * 64 * KVS * 2)

__global__ void __launch_bounds__(128)
attn_kernel() {
    extern __shared__ __half smemh[];
    __half* ksm = smemh;
    __half* vsm = smemh + 2 * 64 * KVS;

    const int qt = blockIdx.x, h = blockIdx.y, b = blockIdx.z;
    const int t = threadIdx.x;
    const int lane = t & 31, w = t >> 5;
    const int r0 = lane >> 2, q4 = lane & 3;

    const size_t kbase = ((size_t)(b * SEQ) * 3 + 1) * DMODEL + h * HDIM;
    const size_t vbase = kbase + DMODEL;
    const int qrow0 = b * SEQ + qt * 64 + w * 16;
    const __half* Qh = g_qkvh + (size_t)qrow0 * 3 * DMODEL + h * HDIM;

    uint32_t qf[4][4];
    #pragma unroll
    for (int s = 0; s < 4; s++) {
        int kk = 16 * s + 2 * q4;
        qf[s][0] = *(const uint32_t*)(Qh + (size_t)(r0    ) * 3072 + kk    );
        qf[s][1] = *(const uint32_t*)(Qh + (size_t)(r0 + 8) * 3072 + kk    );
        qf[s][2] = *(const uint32_t*)(Qh + (size_t)(r0    ) * 3072 + kk + 8);
        qf[s][3] = *(const uint32_t*)(Qh + (size_t)(r0 + 8) * 3072 + kk + 8);
    }

    float of[8][4];
    #pragma unroll
    for (int j = 0; j < 8; j++)
        #pragma unroll
        for (int f = 0; f < 4; f++) of[j][f] = 0.0f;
    float l0 = 0.0f, l1 = 0.0f;   // lane-local partial row sums

    auto loadKV = [&](int k0, int buf) {
        #pragma unroll
        for (int i = 0; i < 4; i++) {
            int idx = t + i * 128;
            int row = idx >> 3, c = idx & 7;
            cpa16(smem_u32(&ksm[buf * 64 * KVS + row * KVS + c * 8]),
                  g_qkvh + kbase + (size_t)(k0 + row) * 3072 + c * 8);
            cpa16(smem_u32(&vsm[buf * 64 * KVS + row * KVS + c * 8]),
                  g_qkvh + vbase + (size_t)(k0 + row) * 3072 + c * 8);
        }
        CP_COMMIT();
    };

    loadKV(0, 0);
    for (int kt = 0; kt < SEQ / 64; kt++) {
        if (kt + 1 < SEQ / 64) {
            loadKV((kt + 1) * 64, (kt + 1) & 1);
            CP_WAIT(1);
        } else {
            CP_WAIT(0);
        }
        __syncthreads();
        const __half* kb = ksm + (kt & 1) * 64 * KVS;
        const __half* vb = vsm + (kt & 1) * 64 * KVS;

        // S = Q K^T
        float sf[8][4];
        #pragma unroll
        for (int j = 0; j < 8; j++)
            #pragma unroll
            for (int f = 0; f < 4; f++) sf[j][f] = 0.0f;
        #pragma unroll
        for (int s = 0; s < 4; s++) {
            #pragma unroll
            for (int np = 0; np < 4; np++) {
                uint32_t bw[4];
                int row = 16 * np + (lane & 7) + 8 * (lane >> 4);
                int col = 16 * s + 8 * ((lane >> 3) & 1);
                ldsm_x4(bw[0], bw[1], bw[2], bw[3], smem_u32(&kb[row * KVS + col]));
                mma_f16(sf[2 * np],     qf[s], &bw[0]);
                mma_f16(sf[2 * np + 1], qf[s], &bw[2]);
            }
        }

        // fixed-max softmax: p = exp2(s); accumulate lane-local sums
        #pragma unroll
        for (int j = 0; j < 8; j++) {
            sf[j][0] = ex2(sf[j][0]);
            sf[j][1] = ex2(sf[j][1]);
            sf[j][2] = ex2(sf[j][2]);
            sf[j][3] = ex2(sf[j][3]);
            l0 += sf[j][0] + sf[j][1];
            l1 += sf[j][2] + sf[j][3];
        }

        // O += P V
        #pragma unroll
        for (int s = 0; s < 4; s++) {
            uint32_t pf[4];
            pf[0] = h2u(__floats2half2_rn(sf[2 * s][0],     sf[2 * s][1]));
            pf[1] = h2u(__floats2half2_rn(sf[2 * s][2],     sf[2 * s][3]));
            pf[2] = h2u(__floats2half2_rn(sf[2 * s + 1][0], sf[2 * s + 1][1]));
            pf[3] = h2u(__floats2half2_rn(sf[2 * s + 1][2], sf[2 * s + 1][3]));
            #pragma unroll
            for (int np = 0; np < 4; np++) {
                uint32_t bw[4];
                int row = 16 * s + (lane & 7) + 8 * ((lane >> 3) & 1);
                int col = 16 * np + 8 * (lane >> 4);
                ldsm_x4_t(bw[0], bw[1], bw[2], bw[3], smem_u32(&vb[row * KVS + col]));
                mma_f16(of[2 * np],     pf, &bw[0]);
                mma_f16(of[2 * np + 1], pf, &bw[2]);
            }
        }
        __syncthreads();
    }

    // single final reduction of row sums over the 4-lane groups
    #pragma unroll
    for (int off = 1; off < 4; off <<= 1) {
        l0 += __shfl_xor_sync(0xffffffffu, l0, off);
        l1 += __shfl_xor_sync(0xffffffffu, l1, off);
    }

    float inv0 = 1.0f / l0, inv1 = 1.0f / l1;
    #pragma unroll
    for (int j = 0; j < 8; j++) {
        size_t base0 = (size_t)(qrow0 + r0    ) * DMODEL + h * HDIM + 8 * j + 2 * q4;
        size_t base1 = (size_t)(qrow0 + r0 + 8) * DMODEL + h * HDIM + 8 * j + 2 * q4;
        *(__half2*)&g_attnh[base0] = __floats2half2_rn(of[j][0] * inv0, of[j][1] * inv0);
        *(__half2*)&g_attnh[base1] = __floats2half2_rn(of[j][2] * inv1, of[j][3] * inv1);
    }
}

// ---------------- launch ----------------
extern "C" void kernel_launch(void* const* d_in, const int* in_sizes, int n_in,
                              void* d_out, int out_size) {
    const float* x       = (const float*)d_in[0];
    const float* cosb    = (const float*)d_in[1];
    const float* sinb    = (const float*)d_in[2];
    const float* c       = (const float*)d_in[3];
    const float* norm1_w = (const float*)d_in[4];
    const float* Wqkv    = (const float*)d_in[5];
    const float* Wout    = (const float*)d_in[6];
    const float* q_norm_w = (const float*)d_in[7];
    const float* k_norm_w = (const float*)d_in[8];
    const float* norm2_w = (const float*)d_in[9];
    const float* W1      = (const float*)d_in[10];
    const float* b1      = (const float*)d_in[11];
    const float* W2      = (const float*)d_in[12];
    const float* b2      = (const float*)d_in[13];
    const float* ada_W   = (const float*)d_in[14];
    const float* ada_b   = (const float*)d_in[15];
    float* out = (float*)d_out;

    float *p_mod, *p_x2;
    __half *p_xnh, *p_qkvh, *p_attnh, *p_hh, *p_wqkvh, *p_wouth, *p_w1h, *p_w2h;
    cudaGetSymbolAddress((void**)&p_mod, g_mod);
    cudaGetSymbolAddress((void**)&p_x2, g_x2);
    cudaGetSymbolAddress((void**)&p_xnh, g_xnh);
    cudaGetSymbolAddress((void**)&p_qkvh, g_qkvh);
    cudaGetSymbolAddress((void**)&p_attnh, g_attnh);
    cudaGetSymbolAddress((void**)&p_hh, g_hh);
    cudaGetSymbolAddress((void**)&p_wqkvh, g_wqkvh);
    cudaGetSymbolAddress((void**)&p_wouth, g_wouth);
    cudaGetSymbolAddress((void**)&p_w1h, g_w1h);
    cudaGetSymbolAddress((void**)&p_w2h, g_w2h);

    cudaFuncSetAttribute(attn_kernel, cudaFuncAttributeMaxDynamicSharedMemorySize, ATTN_SMEM);

    // 0) all weights -> half (single launch)
    cvth_all_kernel<<<R3 / 256, 256>>>(Wqkv, Wout, W1, W2);
    // 1) adaLN modulation vectors
    mod_kernel<<<dim3(MODW / 256, BATCH), 256>>>(c, ada_W, ada_b);
    // 2) LN1 + modulate -> half
    ln_mod_kernel<<<NROWS, 256>>>(x, norm1_w, 0, 1024, p_xnh);
    // 3) qkv = xn @ Wqkv -> half
    mma_gemm_h<0><<<dim3(3 * DMODEL / 128, NROWS / 128), 256>>>(
        p_xnh, p_wqkvh, p_qkvh, NROWS, 3 * DMODEL, DMODEL, nullptr, nullptr, nullptr);
    // 4) rmsnorm + rope (warp-per-head, q pre-scaled)
    rope_kernel<<<NROWS, 512>>>(q_norm_w, k_norm_w, cosb, sinb);
    // 5) attention -> half (fixed-max softmax)
    attn_kernel<<<dim3(SEQ / 64, NHEADS, BATCH), 128, ATTN_SMEM>>>();
    // 6) x2 = x + g_msa * (attn @ Wout)   (fp32 out)
    mma_gemm_h<1><<<dim3(DMODEL / 128, NROWS / 128), 256>>>(
        p_attnh, p_wouth, p_x2, NROWS, DMODEL, DMODEL, x, nullptr, p_mod + 2 * 1024);
    // 7) LN2 + modulate -> half
    ln_mod_kernel<<<NROWS, 256>>>(p_x2, norm2_w, 3 * 1024, 4 * 1024, p_xnh);
    // 8) h = gelu(xn @ W1 + b1) -> half
    mma_gemm_h<2><<<dim3(DFF / 128, NROWS / 128), 256>>>(
        p_xnh, p_w1h, p_hh, NROWS, DFF, DMODEL, nullptr, b1, nullptr);
    // 9) out = x2 + g_mlp * (h @ W2 + b2)  (fp32 out)
    mma_gemm_h<3><<<dim3(DMODEL / 128, NROWS / 128), 256>>>(
        p_hh, p_w2h, out, NROWS, DMODEL, DFF, p_x2, b2, p_mod + 5 * 1024);
}